// round 5
// baseline (speedup 1.0000x reference)
#include <cuda_runtime.h>
#include <math.h>

#define BATCH 256
#define SEQ   300
#define DMODEL 64
#define DFF   256
#define TOKENS (BATCH*SEQ)   // 76800

// Scratch (no allocations allowed -> __device__ globals)
__device__ float g_q[TOKENS*DMODEL];
__device__ float g_k[TOKENS*DMODEL];
__device__ float g_v[TOKENS*DMODEL];
__device__ float g_att[TOKENS*DMODEL];

typedef unsigned long long u64;

// ---- packed fp32x2 helpers (SASS FFMA2 path; ptxas never emits from C++) ----
__device__ __forceinline__ void fma2(u64& acc, u64 a, u64 b) {
    asm("fma.rn.f32x2 %0, %1, %2, %0;" : "+l"(acc) : "l"(a), "l"(b));
}
__device__ __forceinline__ u64 dup2(float x) {
    u64 r; asm("mov.b64 %0, {%1, %1};" : "=l"(r) : "f"(x)); return r;
}
__device__ __forceinline__ u64 pack2(float lo, float hi) {
    u64 r; asm("mov.b64 %0, {%1, %2};" : "=l"(r) : "f"(lo), "f"(hi)); return r;
}
__device__ __forceinline__ float2 unpack2(u64 v) {
    float2 f; asm("mov.b64 {%0, %1}, %2;" : "=f"(f.x), "=f"(f.y) : "l"(v)); return f;
}

__device__ __forceinline__ float gelu_erf(float x) {
    return 0.5f * x * (1.0f + erff(x * 0.70710678118654752f));
}

// ---------------------------------------------------------------------------
// Kernel 1: gated QKV.
// Block = 192 threads (3 projections x 64 channels), tile = 32 tokens
// (halves per-block weight L2 traffic vs 16). Activations token-transposed
// in smem: broadcast LDS.128 = 4 tokens (2 f32x2); weight dup'd once per k.
// ---------------------------------------------------------------------------
#define QTOK 32
#define TPAD 36   // floats per transposed row (32 tokens + pad, 144B = 16B-mult)

__global__ __launch_bounds__(192) void qkv_kernel(
    const float* __restrict__ state, const float* __restrict__ Hin,
    const float* __restrict__ Wq,  const float* __restrict__ bq_,
    const float* __restrict__ Wk,  const float* __restrict__ bk_,
    const float* __restrict__ Wv,  const float* __restrict__ bv_,
    const float* __restrict__ Wcq, const float* __restrict__ bcq,
    const float* __restrict__ Wck, const float* __restrict__ bck,
    const float* __restrict__ Wcv, const float* __restrict__ bcv,
    const float* __restrict__ gQE, const float* __restrict__ bQE,
    const float* __restrict__ gKE, const float* __restrict__ bKE,
    const float* __restrict__ gVE, const float* __restrict__ bVE,
    const float* __restrict__ gQH, const float* __restrict__ bQH,
    const float* __restrict__ gKH, const float* __restrict__ bKH,
    const float* __restrict__ gVH, const float* __restrict__ bVH)
{
    __shared__ __align__(16) float s_tr[64 * TPAD];    // s_tr[k*TPAD + t]
    __shared__ __align__(16) float h_tr[256 * TPAD];   // h_tr[k*TPAD + t]
    __shared__ float red[2][6][QTOK];

    const int tid = threadIdx.x;
    const int p   = tid >> 6;      // 0=q 1=k 2=v
    const int j   = tid & 63;
    const int t0  = blockIdx.x * QTOK;
    const int warpId = tid >> 5;
    const int lane   = tid & 31;

    // transposed fills (global reads coalesced; smem writes one-time)
    for (int i = tid; i < QTOK*64; i += 192) {
        int t = i >> 6, k = i & 63;
        s_tr[k*TPAD + t] = state[(t0+t)*64 + k];
    }
    for (int i = tid; i < QTOK*256; i += 192) {
        int t = i >> 8, k = i & 255;
        h_tr[k*TPAD + t] = Hin[(t0+t)*256 + k];
    }
    __syncthreads();

    const float* WE  = (p==0)?Wq :((p==1)?Wk :Wv);
    const float* bE  = (p==0)?bq_:((p==1)?bk_:bv_);
    const float* WH  = (p==0)?Wcq:((p==1)?Wck:Wcv);
    const float* bH  = (p==0)?bcq:((p==1)?bck:bcv);
    const float* gE  = (p==0)?gQE:((p==1)?gKE:gVE);
    const float* beE = (p==0)?bQE:((p==1)?bKE:bVE);
    const float* gH  = (p==0)?gQH:((p==1)?gKH:gVH);
    const float* beH = (p==0)?bQH:((p==1)?bKH:bVH);

    // ---- H branch GEMM first: H[32x256] @ WH[256x64] (largest loop) ----
    float accH[QTOK];
    {
        u64 acc2[QTOK/2];
        u64 bb = dup2(bH[j]);
        #pragma unroll
        for (int m = 0; m < QTOK/2; m++) acc2[m] = bb;
        #pragma unroll 4
        for (int k = 0; k < 256; k++) {
            u64 w2 = dup2(WH[k*64 + j]);
            const ulonglong2* row = (const ulonglong2*)&h_tr[k*TPAD];
            #pragma unroll
            for (int m = 0; m < QTOK/4; m++) {
                ulonglong2 x = row[m];          // tokens 4m..4m+3 (broadcast)
                fma2(acc2[2*m+0], w2, x.x);
                fma2(acc2[2*m+1], w2, x.y);
            }
        }
        #pragma unroll
        for (int m = 0; m < QTOK/2; m++) {
            float2 f = unpack2(acc2[m]);
            accH[2*m] = f.x; accH[2*m+1] = f.y;
        }
    }

    // ---- E branch GEMM: state[32x64] @ WE[64x64] ----
    float accE[QTOK];
    {
        u64 acc2[QTOK/2];
        u64 bb = dup2(bE[j]);
        #pragma unroll
        for (int m = 0; m < QTOK/2; m++) acc2[m] = bb;
        #pragma unroll 4
        for (int k = 0; k < 64; k++) {
            u64 w2 = dup2(WE[k*64 + j]);
            const ulonglong2* row = (const ulonglong2*)&s_tr[k*TPAD];
            #pragma unroll
            for (int m = 0; m < QTOK/4; m++) {
                ulonglong2 x = row[m];
                fma2(acc2[2*m+0], w2, x.x);
                fma2(acc2[2*m+1], w2, x.y);
            }
        }
        #pragma unroll
        for (int m = 0; m < QTOK/2; m++) {
            float2 f = unpack2(acc2[m]);
            accE[2*m] = f.x; accE[2*m+1] = f.y;
        }
    }

    // ---- LayerNorm E over 64 channels (2 warps share one projection) ----
    #pragma unroll
    for (int t = 0; t < QTOK; t++) {
        float s1 = accE[t], s2 = accE[t]*accE[t];
        #pragma unroll
        for (int o = 16; o; o >>= 1) {
            s1 += __shfl_xor_sync(0xffffffffu, s1, o);
            s2 += __shfl_xor_sync(0xffffffffu, s2, o);
        }
        if (lane == 0) { red[0][warpId][t] = s1; red[1][warpId][t] = s2; }
    }
    __syncthreads();
    {
        float gj = gE[j], bj = beE[j];
        #pragma unroll
        for (int t = 0; t < QTOK; t++) {
            float s1 = red[0][2*p][t] + red[0][2*p+1][t];
            float s2 = red[1][2*p][t] + red[1][2*p+1][t];
            float m  = s1 * (1.0f/64.0f);
            float var = s2 * (1.0f/64.0f) - m*m;
            float r  = rsqrtf(var + 1e-5f);
            accE[t] = (accE[t] - m) * r * gj + bj;
        }
    }
    __syncthreads();

    // ---- LayerNorm H ----
    #pragma unroll
    for (int t = 0; t < QTOK; t++) {
        float s1 = accH[t], s2 = accH[t]*accH[t];
        #pragma unroll
        for (int o = 16; o; o >>= 1) {
            s1 += __shfl_xor_sync(0xffffffffu, s1, o);
            s2 += __shfl_xor_sync(0xffffffffu, s2, o);
        }
        if (lane == 0) { red[0][warpId][t] = s1; red[1][warpId][t] = s2; }
    }
    __syncthreads();
    {
        float gj = gH[j], bj = beH[j];
        #pragma unroll
        for (int t = 0; t < QTOK; t++) {
            float s1 = red[0][2*p][t] + red[0][2*p+1][t];
            float s2 = red[1][2*p][t] + red[1][2*p+1][t];
            float m  = s1 * (1.0f/64.0f);
            float var = s2 * (1.0f/64.0f) - m*m;
            float r  = rsqrtf(var + 1e-5f);
            accH[t] = (accH[t] - m) * r * gj + bj;
        }
    }

    float* outp = (p==0) ? g_q : ((p==1) ? g_k : g_v);
    #pragma unroll
    for (int t = 0; t < QTOK; t++)
        outp[(t0+t)*64 + j] = accE[t] * accH[t];
}

// ---------------------------------------------------------------------------
// Kernel 2: attention. grid = (10 query-tiles, 512 (b,h) pairs), 256 threads.
// K stored as packed pairs (kj, kj+150) -> one LDS.64 = one f32x2 operand.
// V stored d-major (row stride 308 floats -> conflict-free LDS.128);
// consecutive kj adjacent -> float4 = two f32x2 operands, zero pack MOVs.
// ---------------------------------------------------------------------------
#define K2_FLOATS   (150*33*2)        // 9900
#define VTR_STRIDE  308               // floats per d-row (300 + pad)
#define VTR_FLOATS  (32*VTR_STRIDE)   // 9856
#define Q_FLOATS    (32*33)           // 1056
#define P_FLOATS    (32*300)          // 9600
#define ATTN_SMEM_FLOATS (K2_FLOATS + VTR_FLOATS + Q_FLOATS + P_FLOATS)

__global__ __launch_bounds__(256, 1) void attn_kernel()
{
    extern __shared__ __align__(16) float sm[];
    float* k2f  = sm;                     // [150][33] float2 (pairs kj, kj+150)
    float* v_tr = k2f + K2_FLOATS;        // [32][308]
    float* q_sm = v_tr + VTR_FLOATS;      // [32][33]
    float* p_sm = q_sm + Q_FLOATS;        // [32][300]

    const int tid  = threadIdx.x;
    const int pair = blockIdx.y;
    const int b = pair >> 1, h = pair & 1;
    const int q0 = blockIdx.x * 32;

    const float* kg = g_k + (b*SEQ)*64 + h*32;
    const float* vg = g_v + (b*SEQ)*64 + h*32;
    const float* qg = g_q + (b*SEQ)*64 + h*32;

    // K pairs: k2[kj][d] = (K[kj][d], K[kj+150][d])
    for (int i = tid; i < 150*32; i += 256) {
        int kj = i >> 5, d = i & 31;
        float lo = kg[kj*64 + d];
        float hi = kg[(kj+150)*64 + d];
        ((float2*)k2f)[kj*33 + d] = make_float2(lo, hi);
    }
    // V transposed: v_tr[d][s]
    for (int i = tid; i < SEQ*32; i += 256) {
        int s = i >> 5, d = i & 31;
        v_tr[d*VTR_STRIDE + s] = vg[s*64 + d];
    }
    for (int i = tid; i < 32*32; i += 256) {
        int r = i >> 5, d = i & 31;
        int sr = q0 + r;
        q_sm[r*33+d] = (sr < SEQ) ? qg[sr*64+d] : 0.0f;
    }
    __syncthreads();

    // ---- scores: Q[32x32] @ K^T[32x300], 4x4 tiles, K pairs pre-packed ----
    const float scale = 0.17677669529663689f;   // 1/sqrt(32)
    {
        const u64* k2u = (const u64*)k2f;
        const int tx = tid & 31;   // key lane
        const int ty = tid >> 5;   // query quad: rows 4*ty .. 4*ty+3
        #pragma unroll
        for (int pp = 0; pp < 3; pp++) {
            int kbase = tx + 32*pp;           // covers [0,75) across pp
            if (kbase < 75) {
                u64 accp[4][2];
                #pragma unroll
                for (int qi = 0; qi < 4; qi++) { accp[qi][0] = 0ULL; accp[qi][1] = 0ULL; }
                #pragma unroll 8
                for (int d = 0; d < 32; d++) {
                    u64 kpA = k2u[(kbase     )*33 + d];  // (K[kbase],   K[kbase+150])
                    u64 kpB = k2u[(kbase + 75)*33 + d];  // (K[kbase+75],K[kbase+225])
                    #pragma unroll
                    for (int qi = 0; qi < 4; qi++) {
                        u64 qd = dup2(q_sm[(4*ty+qi)*33 + d]);  // broadcast
                        fma2(accp[qi][0], qd, kpA);
                        fma2(accp[qi][1], qd, kpB);
                    }
                }
                #pragma unroll
                for (int qi = 0; qi < 4; qi++) {
                    float2 aA = unpack2(accp[qi][0]);   // keys kbase, kbase+150
                    float2 aB = unpack2(accp[qi][1]);   // keys kbase+75, kbase+225
                    float* prow = p_sm + (4*ty+qi)*SEQ + kbase;
                    prow[  0] = aA.x * scale;
                    prow[150] = aA.y * scale;
                    prow[ 75] = aB.x * scale;
                    prow[225] = aB.y * scale;
                }
            }
        }
    }
    __syncthreads();

    // softmax: warp w handles rows w, w+8, w+16, w+24
    const int warpId = tid >> 5, lane = tid & 31;
    for (int r = warpId; r < 32; r += 8) {
        float mx = -1e30f;
        for (int c = lane; c < SEQ; c += 32) mx = fmaxf(mx, p_sm[r*SEQ+c]);
        #pragma unroll
        for (int o = 16; o; o >>= 1) mx = fmaxf(mx, __shfl_xor_sync(0xffffffffu, mx, o));
        float sum = 0.0f;
        for (int c = lane; c < SEQ; c += 32) {
            float e = __expf(p_sm[r*SEQ+c] - mx);
            p_sm[r*SEQ+c] = e;
            sum += e;
        }
        #pragma unroll
        for (int o = 16; o; o >>= 1) sum += __shfl_xor_sync(0xffffffffu, sum, o);
        float inv = 1.0f / sum;
        for (int c = lane; c < SEQ; c += 32) p_sm[r*SEQ+c] *= inv;
    }
    __syncthreads();

    // O = P @ V : thread (qg8 = warp, d = lane), 4 query rows.
    // P rows are warp-broadcast LDS.128; V is one LDS.128 per 4 kj.
    const int d = tid & 31, qg8 = tid >> 5;
    u64 accP[4] = {0ULL, 0ULL, 0ULL, 0ULL};
    for (int kj = 0; kj < SEQ; kj += 4) {
        ulonglong2 vp = *(const ulonglong2*)&v_tr[d*VTR_STRIDE + kj];
        #pragma unroll
        for (int i = 0; i < 4; i++) {
            ulonglong2 pl = *(const ulonglong2*)&p_sm[(qg8 + 8*i)*SEQ + kj];
            fma2(accP[i], pl.x, vp.x);
            fma2(accP[i], pl.y, vp.y);
        }
    }
    #pragma unroll
    for (int i = 0; i < 4; i++) {
        float2 f = unpack2(accP[i]);
        int qi = qg8 + 8*i;
        int sr = q0 + qi;
        if (sr < SEQ)
            g_att[(b*SEQ+sr)*64 + h*32 + d] = f.x + f.y;
    }
}

// ---------------------------------------------------------------------------
// Kernel 3: Z1 = state+att; Z2 = LN(Z1); h = gelu(Z2@W1+b1); out = Z1 + h@W2+b2
// Block = 256 threads, 16 tokens. Weight float4 LDGs reinterpret as 2 f32x2.
// ---------------------------------------------------------------------------
__global__ __launch_bounds__(256) void ffn_kernel(
    const float* __restrict__ state,
    const float* __restrict__ W1, const float* __restrict__ b1,
    const float* __restrict__ W2, const float* __restrict__ b2,
    const float* __restrict__ g1, const float* __restrict__ beta1,
    float* __restrict__ out)
{
    __shared__ __align__(16) float z1_sm[16][64];
    __shared__ __align__(16) float z2_sm[16][64];
    __shared__ __align__(16) float hh_sm[16][256];
    __shared__ float red[2][8][4];

    const int tid = threadIdx.x;
    const int t0  = blockIdx.x * 16;
    const int ch  = tid & 63;
    const int tq  = tid >> 6;     // 0..3
    const int warpId = tid >> 5, lane = tid & 31;

    // phase 1: residual + LN over 64 channels
    float z1v[4];
    #pragma unroll
    for (int i = 0; i < 4; i++) {
        int t = tq + 4*i;
        int idx = (t0+t)*64 + ch;
        float z = state[idx] + g_att[idx];
        z1v[i] = z;
        z1_sm[t][ch] = z;
    }
    #pragma unroll
    for (int i = 0; i < 4; i++) {
        float s1 = z1v[i], s2 = z1v[i]*z1v[i];
        #pragma unroll
        for (int o = 16; o; o >>= 1) {
            s1 += __shfl_xor_sync(0xffffffffu, s1, o);
            s2 += __shfl_xor_sync(0xffffffffu, s2, o);
        }
        if (lane == 0) { red[0][warpId][i] = s1; red[1][warpId][i] = s2; }
    }
    __syncthreads();
    {
        float gj = g1[ch], bj = beta1[ch];
        #pragma unroll
        for (int i = 0; i < 4; i++) {
            float s1 = red[0][2*tq][i] + red[0][2*tq+1][i];
            float s2 = red[1][2*tq][i] + red[1][2*tq+1][i];
            float m   = s1 * (1.0f/64.0f);
            float var = s2 * (1.0f/64.0f) - m*m;
            float r   = rsqrtf(var + 1e-5f);
            z2_sm[tq+4*i][ch] = (z1v[i] - m) * r * gj + bj;
        }
    }
    __syncthreads();

    // phase 2: hidden = gelu(Z2 @ W1 + b1); thread (tok, jb) owns 16 channels
    const int tok = tid >> 4;
    const int jb  = tid & 15;
    u64 ha2[8];
    #pragma unroll
    for (int i = 0; i < 4; i++) {
        float4 bb = *(const float4*)&b1[4*jb + 64*i];
        ha2[2*i+0] = pack2(bb.x, bb.y);
        ha2[2*i+1] = pack2(bb.z, bb.w);
    }
    #pragma unroll 4
    for (int k = 0; k < 64; k++) {
        u64 zd = dup2(z2_sm[tok][k]);
        #pragma unroll
        for (int i = 0; i < 4; i++) {
            ulonglong2 w = *(const ulonglong2*)&W1[k*256 + 4*jb + 64*i];
            fma2(ha2[2*i+0], w.x, zd);
            fma2(ha2[2*i+1], w.y, zd);
        }
    }
    #pragma unroll
    for (int i = 0; i < 4; i++) {
        int j = 4*jb + 64*i;
        float2 lo = unpack2(ha2[2*i+0]);
        float2 hi = unpack2(ha2[2*i+1]);
        hh_sm[tok][j+0] = gelu_erf(lo.x);
        hh_sm[tok][j+1] = gelu_erf(lo.y);
        hh_sm[tok][j+2] = gelu_erf(hi.x);
        hh_sm[tok][j+3] = gelu_erf(hi.y);
    }
    __syncthreads();

    // phase 3: Z4 = hidden @ W2 + b2; out = Z1 + Z4
    // hh loaded as LDS.64 (broadcast) -> 1 LDS + 2 dup per 2 js.
    const int c = 4*(tid & 15);
    u64 oa[4];
    {
        float4 bb = *(const float4*)&b2[c];
        oa[0] = pack2(bb.x, bb.y);
        oa[1] = pack2(bb.z, bb.w);
        oa[2] = 0ULL;
        oa[3] = 0ULL;
    }
    #pragma unroll 4
    for (int jj = 0; jj < 256; jj += 2) {
        float2 hp = *(const float2*)&hh_sm[tok][jj];
        u64 h0d = dup2(hp.x);
        u64 h1d = dup2(hp.y);
        ulonglong2 w0 = *(const ulonglong2*)&W2[jj*64 + c];
        ulonglong2 w1 = *(const ulonglong2*)&W2[(jj+1)*64 + c];
        fma2(oa[0], w0.x, h0d);
        fma2(oa[1], w0.y, h0d);
        fma2(oa[2], w1.x, h1d);
        fma2(oa[3], w1.y, h1d);
    }
    float2 oA = unpack2(oa[0]), oB = unpack2(oa[1]);
    float2 oC = unpack2(oa[2]), oD = unpack2(oa[3]);
    float4 z1r = *(const float4*)&z1_sm[tok][c];
    float4 res;
    res.x = z1r.x + oA.x + oC.x;
    res.y = z1r.y + oA.y + oC.y;
    res.z = z1r.z + oB.x + oD.x;
    res.w = z1r.w + oB.y + oD.y;
    *(float4*)&out[(t0+tok)*64 + c] = res;
}

// ---------------------------------------------------------------------------
extern "C" void kernel_launch(void* const* d_in, const int* in_sizes, int n_in,
                              void* d_out, int out_size)
{
    const float* state = (const float*)d_in[0];
    const float* Hin   = (const float*)d_in[1];
    const float* Wq  = (const float*)d_in[2];  const float* bq  = (const float*)d_in[3];
    const float* Wk  = (const float*)d_in[4];  const float* bk  = (const float*)d_in[5];
    const float* Wv  = (const float*)d_in[6];  const float* bv  = (const float*)d_in[7];
    const float* Wcq = (const float*)d_in[8];  const float* bcq = (const float*)d_in[9];
    const float* Wck = (const float*)d_in[10]; const float* bck = (const float*)d_in[11];
    const float* Wcv = (const float*)d_in[12]; const float* bcv = (const float*)d_in[13];
    const float* gQE = (const float*)d_in[14]; const float* bQE = (const float*)d_in[15];
    const float* gKE = (const float*)d_in[16]; const float* bKE = (const float*)d_in[17];
    const float* gVE = (const float*)d_in[18]; const float* bVE = (const float*)d_in[19];
    const float* gQH = (const float*)d_in[20]; const float* bQH = (const float*)d_in[21];
    const float* gKH = (const float*)d_in[22]; const float* bKH = (const float*)d_in[23];
    const float* gVH = (const float*)d_in[24]; const float* bVH = (const float*)d_in[25];
    const float* W1  = (const float*)d_in[26]; const float* b1  = (const float*)d_in[27];
    const float* W2  = (const float*)d_in[28]; const float* b2  = (const float*)d_in[29];
    const float* g1  = (const float*)d_in[30]; const float* be1 = (const float*)d_in[31];
    float* out = (float*)d_out;

    const int attn_smem = ATTN_SMEM_FLOATS * (int)sizeof(float);   // 121648 B
    cudaFuncSetAttribute(attn_kernel,
                         cudaFuncAttributeMaxDynamicSharedMemorySize, attn_smem);

    qkv_kernel<<<TOKENS/QTOK, 192>>>(state, Hin,
        Wq, bq, Wk, bk, Wv, bv, Wcq, bcq, Wck, bck, Wcv, bcv,
        gQE, bQE, gKE, bKE, gVE, bVE, gQH, bQH, gKH, bKH, gVH, bVH);

    attn_kernel<<<dim3(10, BATCH*2), 256, attn_smem>>>();

    ffn_kernel<<<TOKENS/16, 256>>>(state, W1, b1, W2, b2, g1, be1, out);
}

// round 6
// speedup vs baseline: 1.4895x; 1.4895x over previous
#include <cuda_runtime.h>
#include <math.h>

#define BATCH 256
#define SEQ   300
#define DMODEL 64
#define DFF   256
#define TOKENS (BATCH*SEQ)   // 76800

__device__ float g_q[TOKENS*DMODEL];
__device__ float g_k[TOKENS*DMODEL];
__device__ float g_v[TOKENS*DMODEL];
__device__ float g_att[TOKENS*DMODEL];

typedef unsigned long long u64;

__device__ __forceinline__ void fma2(u64& acc, u64 a, u64 b) {
    asm("fma.rn.f32x2 %0, %1, %2, %0;" : "+l"(acc) : "l"(a), "l"(b));
}
__device__ __forceinline__ u64 dup2(float x) {
    u64 r; asm("mov.b64 %0, {%1, %1};" : "=l"(r) : "f"(x)); return r;
}
__device__ __forceinline__ float2 unpack2(u64 v) {
    float2 f; asm("mov.b64 {%0, %1}, %2;" : "=f"(f.x), "=f"(f.y) : "l"(v)); return f;
}
__device__ __forceinline__ float gelu_erf(float x) {
    return 0.5f * x * (1.0f + erff(x * 0.70710678118654752f));
}

// ---------------------------------------------------------------------------
// Kernel 1: gated QKV. Block = 192 threads (3 proj x 64), 32 tokens.
// Thread tile: 4 tokens x 8 channels. Weights via LDG.128 = 2 native f32x2
// (zero dup); activations via one broadcast LDS.128 + 4 dups. 16 FFMA2 / k.
// LayerNorm is warp-local (8-lane shfl groups) - no smem reduction.
// ---------------------------------------------------------------------------
#define QTOK 32
#define TPAD 36

__global__ __launch_bounds__(192) void qkv_kernel(
    const float* __restrict__ state, const float* __restrict__ Hin,
    const float* __restrict__ Wq,  const float* __restrict__ bq_,
    const float* __restrict__ Wk,  const float* __restrict__ bk_,
    const float* __restrict__ Wv,  const float* __restrict__ bv_,
    const float* __restrict__ Wcq, const float* __restrict__ bcq,
    const float* __restrict__ Wck, const float* __restrict__ bck,
    const float* __restrict__ Wcv, const float* __restrict__ bcv,
    const float* __restrict__ gQE, const float* __restrict__ bQE,
    const float* __restrict__ gKE, const float* __restrict__ bKE,
    const float* __restrict__ gVE, const float* __restrict__ bVE,
    const float* __restrict__ gQH, const float* __restrict__ bQH,
    const float* __restrict__ gKH, const float* __restrict__ bKH,
    const float* __restrict__ gVH, const float* __restrict__ bVH)
{
    __shared__ __align__(16) float s_tr[64 * TPAD];    // [k][tok]
    __shared__ __align__(16) float h_tr[256 * TPAD];   // [k][tok]

    const int tid = threadIdx.x;
    const int p   = tid >> 6;          // projection 0=q 1=k 2=v
    const int q   = tid & 63;
    const int ty  = q >> 3;            // token quad 0..7
    const int tx  = q & 7;             // channel octet 0..7
    const int ch0 = tx * 8;
    const int t0  = blockIdx.x * QTOK;

    for (int i = tid; i < QTOK*64; i += 192) {
        int t = i >> 6, k = i & 63;
        s_tr[k*TPAD + t] = state[(t0+t)*64 + k];
    }
    for (int i = tid; i < QTOK*256; i += 192) {
        int t = i >> 8, k = i & 255;
        h_tr[k*TPAD + t] = Hin[(t0+t)*256 + k];
    }
    __syncthreads();

    const float* WE  = (p==0)?Wq :((p==1)?Wk :Wv);
    const float* bE  = (p==0)?bq_:((p==1)?bk_:bv_);
    const float* WH  = (p==0)?Wcq:((p==1)?Wck:Wcv);
    const float* bH  = (p==0)?bcq:((p==1)?bck:bcv);
    const float* gE  = (p==0)?gQE:((p==1)?gKE:gVE);
    const float* beE = (p==0)?bQE:((p==1)?bKE:bVE);
    const float* gH  = (p==0)?gQH:((p==1)?gKH:gVH);
    const float* beH = (p==0)?bQH:((p==1)?bKH:bVH);

    // ---- E branch GEMM: state[32x64] @ WE[64x64] ----
    float accE[4][8];
    {
        u64 acc[4][4];
        ulonglong2 bb0 = *(const ulonglong2*)&bE[ch0];
        ulonglong2 bb1 = *(const ulonglong2*)&bE[ch0+4];
        #pragma unroll
        for (int t = 0; t < 4; t++) {
            acc[t][0] = bb0.x; acc[t][1] = bb0.y;
            acc[t][2] = bb1.x; acc[t][3] = bb1.y;
        }
        #pragma unroll 2
        for (int k = 0; k < 64; k++) {
            float4 a = *(const float4*)&s_tr[k*TPAD + 4*ty];
            u64 ad0 = dup2(a.x), ad1 = dup2(a.y), ad2 = dup2(a.z), ad3 = dup2(a.w);
            ulonglong2 w01 = *(const ulonglong2*)&WE[k*64 + ch0];
            ulonglong2 w23 = *(const ulonglong2*)&WE[k*64 + ch0 + 4];
            fma2(acc[0][0], ad0, w01.x); fma2(acc[0][1], ad0, w01.y);
            fma2(acc[0][2], ad0, w23.x); fma2(acc[0][3], ad0, w23.y);
            fma2(acc[1][0], ad1, w01.x); fma2(acc[1][1], ad1, w01.y);
            fma2(acc[1][2], ad1, w23.x); fma2(acc[1][3], ad1, w23.y);
            fma2(acc[2][0], ad2, w01.x); fma2(acc[2][1], ad2, w01.y);
            fma2(acc[2][2], ad2, w23.x); fma2(acc[2][3], ad2, w23.y);
            fma2(acc[3][0], ad3, w01.x); fma2(acc[3][1], ad3, w01.y);
            fma2(acc[3][2], ad3, w23.x); fma2(acc[3][3], ad3, w23.y);
        }
        #pragma unroll
        for (int t = 0; t < 4; t++)
            #pragma unroll
            for (int c = 0; c < 4; c++) {
                float2 f = unpack2(acc[t][c]);
                accE[t][2*c] = f.x; accE[t][2*c+1] = f.y;
            }
    }
    // LN E: warp-local over 8-lane tx groups (64 channels total)
    {
        float4 g0 = *(const float4*)&gE[ch0],  g1v = *(const float4*)&gE[ch0+4];
        float4 b0 = *(const float4*)&beE[ch0], b1v = *(const float4*)&beE[ch0+4];
        float gv[8] = {g0.x,g0.y,g0.z,g0.w,g1v.x,g1v.y,g1v.z,g1v.w};
        float bv[8] = {b0.x,b0.y,b0.z,b0.w,b1v.x,b1v.y,b1v.z,b1v.w};
        #pragma unroll
        for (int t = 0; t < 4; t++) {
            float s1 = 0.f, s2 = 0.f;
            #pragma unroll
            for (int c = 0; c < 8; c++) { s1 += accE[t][c]; s2 += accE[t][c]*accE[t][c]; }
            #pragma unroll
            for (int o = 1; o < 8; o <<= 1) {
                s1 += __shfl_xor_sync(0xffffffffu, s1, o);
                s2 += __shfl_xor_sync(0xffffffffu, s2, o);
            }
            float m = s1 * (1.0f/64.0f);
            float var = s2 * (1.0f/64.0f) - m*m;
            float r = rsqrtf(var + 1e-5f);
            #pragma unroll
            for (int c = 0; c < 8; c++)
                accE[t][c] = (accE[t][c] - m) * r * gv[c] + bv[c];
        }
    }

    // ---- H branch GEMM: H[32x256] @ WH[256x64] ----
    float accH[4][8];
    {
        u64 acc[4][4];
        ulonglong2 bb0 = *(const ulonglong2*)&bH[ch0];
        ulonglong2 bb1 = *(const ulonglong2*)&bH[ch0+4];
        #pragma unroll
        for (int t = 0; t < 4; t++) {
            acc[t][0] = bb0.x; acc[t][1] = bb0.y;
            acc[t][2] = bb1.x; acc[t][3] = bb1.y;
        }
        #pragma unroll 2
        for (int k = 0; k < 256; k++) {
            float4 a = *(const float4*)&h_tr[k*TPAD + 4*ty];
            u64 ad0 = dup2(a.x), ad1 = dup2(a.y), ad2 = dup2(a.z), ad3 = dup2(a.w);
            ulonglong2 w01 = *(const ulonglong2*)&WH[k*64 + ch0];
            ulonglong2 w23 = *(const ulonglong2*)&WH[k*64 + ch0 + 4];
            fma2(acc[0][0], ad0, w01.x); fma2(acc[0][1], ad0, w01.y);
            fma2(acc[0][2], ad0, w23.x); fma2(acc[0][3], ad0, w23.y);
            fma2(acc[1][0], ad1, w01.x); fma2(acc[1][1], ad1, w01.y);
            fma2(acc[1][2], ad1, w23.x); fma2(acc[1][3], ad1, w23.y);
            fma2(acc[2][0], ad2, w01.x); fma2(acc[2][1], ad2, w01.y);
            fma2(acc[2][2], ad2, w23.x); fma2(acc[2][3], ad2, w23.y);
            fma2(acc[3][0], ad3, w01.x); fma2(acc[3][1], ad3, w01.y);
            fma2(acc[3][2], ad3, w23.x); fma2(acc[3][3], ad3, w23.y);
        }
        #pragma unroll
        for (int t = 0; t < 4; t++)
            #pragma unroll
            for (int c = 0; c < 4; c++) {
                float2 f = unpack2(acc[t][c]);
                accH[t][2*c] = f.x; accH[t][2*c+1] = f.y;
            }
    }
    // LN H
    {
        float4 g0 = *(const float4*)&gH[ch0],  g1v = *(const float4*)&gH[ch0+4];
        float4 b0 = *(const float4*)&beH[ch0], b1v = *(const float4*)&beH[ch0+4];
        float gv[8] = {g0.x,g0.y,g0.z,g0.w,g1v.x,g1v.y,g1v.z,g1v.w};
        float bv[8] = {b0.x,b0.y,b0.z,b0.w,b1v.x,b1v.y,b1v.z,b1v.w};
        #pragma unroll
        for (int t = 0; t < 4; t++) {
            float s1 = 0.f, s2 = 0.f;
            #pragma unroll
            for (int c = 0; c < 8; c++) { s1 += accH[t][c]; s2 += accH[t][c]*accH[t][c]; }
            #pragma unroll
            for (int o = 1; o < 8; o <<= 1) {
                s1 += __shfl_xor_sync(0xffffffffu, s1, o);
                s2 += __shfl_xor_sync(0xffffffffu, s2, o);
            }
            float m = s1 * (1.0f/64.0f);
            float var = s2 * (1.0f/64.0f) - m*m;
            float r = rsqrtf(var + 1e-5f);
            #pragma unroll
            for (int c = 0; c < 8; c++)
                accH[t][c] = (accH[t][c] - m) * r * gv[c] + bv[c];
        }
    }

    float* outp = (p==0) ? g_q : ((p==1) ? g_k : g_v);
    #pragma unroll
    for (int t = 0; t < 4; t++) {
        int row = (t0 + 4*ty + t) * 64 + ch0;
        *(float4*)&outp[row]   = make_float4(accE[t][0]*accH[t][0], accE[t][1]*accH[t][1],
                                             accE[t][2]*accH[t][2], accE[t][3]*accH[t][3]);
        *(float4*)&outp[row+4] = make_float4(accE[t][4]*accH[t][4], accE[t][5]*accH[t][5],
                                             accE[t][6]*accH[t][6], accE[t][7]*accH[t][7]);
    }
}

// ---------------------------------------------------------------------------
// Kernel 2: attention. K (scores) and V (PV) alias the same smem region:
// V is loaded from global AFTER the scores sync, overlapped with softmax.
// smem 82.2 KB -> 2 blocks/SM.
// ---------------------------------------------------------------------------
#define REGA_FLOATS (150*33*2)        // 9900 (k2); v_tr needs 32*308=9856 <= this
#define VTR_STRIDE  308
#define Q_FLOATS    (32*33)
#define P_FLOATS    (32*300)
#define ATTN_SMEM_FLOATS (REGA_FLOATS + Q_FLOATS + P_FLOATS)   // 20556

__global__ __launch_bounds__(256, 2) void attn_kernel()
{
    extern __shared__ __align__(16) float sm[];
    float* k2f  = sm;                     // [150][33] float2 pairs (kj, kj+150)
    float* v_tr = sm;                     // [32][308]  (after scores)
    float* q_sm = sm + REGA_FLOATS;       // [32][33]
    float* p_sm = q_sm + Q_FLOATS;        // [32][300]

    const int tid  = threadIdx.x;
    const int pair = blockIdx.y;
    const int b = pair >> 1, h = pair & 1;
    const int q0 = blockIdx.x * 32;

    const float* kg = g_k + (b*SEQ)*64 + h*32;
    const float* vg = g_v + (b*SEQ)*64 + h*32;
    const float* qg = g_q + (b*SEQ)*64 + h*32;

    for (int i = tid; i < 150*32; i += 256) {
        int kj = i >> 5, d = i & 31;
        float lo = kg[kj*64 + d];
        float hi = kg[(kj+150)*64 + d];
        ((float2*)k2f)[kj*33 + d] = make_float2(lo, hi);
    }
    for (int i = tid; i < 32*32; i += 256) {
        int r = i >> 5, d = i & 31;
        int sr = q0 + r;
        q_sm[r*33+d] = (sr < SEQ) ? qg[sr*64+d] : 0.0f;
    }
    __syncthreads();

    // ---- scores: Q[32x32] @ K^T[32x300] ----
    const float scale = 0.17677669529663689f;
    {
        const u64* k2u = (const u64*)k2f;
        const int tx = tid & 31;
        const int ty = tid >> 5;
        #pragma unroll
        for (int pp = 0; pp < 3; pp++) {
            int kbase = tx + 32*pp;
            if (kbase < 75) {
                u64 accp[4][2];
                #pragma unroll
                for (int qi = 0; qi < 4; qi++) { accp[qi][0] = 0ULL; accp[qi][1] = 0ULL; }
                #pragma unroll 8
                for (int d = 0; d < 32; d++) {
                    u64 kpA = k2u[(kbase     )*33 + d];
                    u64 kpB = k2u[(kbase + 75)*33 + d];
                    #pragma unroll
                    for (int qi = 0; qi < 4; qi++) {
                        u64 qd = dup2(q_sm[(4*ty+qi)*33 + d]);
                        fma2(accp[qi][0], qd, kpA);
                        fma2(accp[qi][1], qd, kpB);
                    }
                }
                #pragma unroll
                for (int qi = 0; qi < 4; qi++) {
                    float2 aA = unpack2(accp[qi][0]);
                    float2 aB = unpack2(accp[qi][1]);
                    float* prow = p_sm + (4*ty+qi)*SEQ + kbase;
                    prow[  0] = aA.x * scale;
                    prow[150] = aA.y * scale;
                    prow[ 75] = aB.x * scale;
                    prow[225] = aB.y * scale;
                }
            }
        }
    }
    __syncthreads();   // scores done; k2 region now dead

    // ---- V fill (overwrites k2 region) overlapped with softmax ----
    for (int i = tid; i < SEQ*32; i += 256) {
        int s = i >> 5, d = i & 31;
        v_tr[d*VTR_STRIDE + s] = vg[s*64 + d];
    }
    const int warpId = tid >> 5, lane = tid & 31;
    for (int r = warpId; r < 32; r += 8) {
        float mx = -1e30f;
        for (int c = lane; c < SEQ; c += 32) mx = fmaxf(mx, p_sm[r*SEQ+c]);
        #pragma unroll
        for (int o = 16; o; o >>= 1) mx = fmaxf(mx, __shfl_xor_sync(0xffffffffu, mx, o));
        float sum = 0.0f;
        for (int c = lane; c < SEQ; c += 32) {
            float e = __expf(p_sm[r*SEQ+c] - mx);
            p_sm[r*SEQ+c] = e;
            sum += e;
        }
        #pragma unroll
        for (int o = 16; o; o >>= 1) sum += __shfl_xor_sync(0xffffffffu, sum, o);
        float inv = 1.0f / sum;
        for (int c = lane; c < SEQ; c += 32) p_sm[r*SEQ+c] *= inv;
    }
    __syncthreads();

    // ---- O = P @ V ----
    const int d = tid & 31, qg8 = tid >> 5;
    u64 accP[4] = {0ULL, 0ULL, 0ULL, 0ULL};
    for (int kj = 0; kj < SEQ; kj += 4) {
        ulonglong2 vp = *(const ulonglong2*)&v_tr[d*VTR_STRIDE + kj];
        #pragma unroll
        for (int i = 0; i < 4; i++) {
            ulonglong2 pl = *(const ulonglong2*)&p_sm[(qg8 + 8*i)*SEQ + kj];
            fma2(accP[i], pl.x, vp.x);
            fma2(accP[i], pl.y, vp.y);
        }
    }
    #pragma unroll
    for (int i = 0; i < 4; i++) {
        float2 f = unpack2(accP[i]);
        int qi = qg8 + 8*i;
        int sr = q0 + qi;
        if (sr < SEQ)
            g_att[(b*SEQ+sr)*64 + h*32 + d] = f.x + f.y;
    }
}

// ---------------------------------------------------------------------------
// Kernel 3: FFN. 32-token blocks, 256 threads.
// Phase2: warps partition hidden channels (32 each); thread 4 tok x 8 ch.
// Phase3: warp covers all 64 out channels; thread 2 tok x 4 ch.
// ---------------------------------------------------------------------------
#define Z2S 65
#define HHS 260
#define FFN_SMEM_FLOATS (32*64 + 32*Z2S + 32*HHS)   // 2048+2080+8320 = 12448

__global__ __launch_bounds__(256) void ffn_kernel(
    const float* __restrict__ state,
    const float* __restrict__ W1, const float* __restrict__ b1,
    const float* __restrict__ W2, const float* __restrict__ b2,
    const float* __restrict__ g1, const float* __restrict__ beta1,
    float* __restrict__ out)
{
    extern __shared__ __align__(16) float fsm[];
    float* z1s = fsm;                 // [32][64]
    float* z2s = fsm + 2048;          // [32][65]
    float* hhs = fsm + 2048 + 2080;   // [32][260]

    const int tid = threadIdx.x;
    const int t0  = blockIdx.x * 32;

    // ---- phase1: residual + LN (thread: 1 token, 8 channels) ----
    {
        int tok = tid >> 3, c8 = (tid & 7) * 8;
        int base = (t0 + tok) * 64 + c8;
        float4 sa = *(const float4*)&state[base];
        float4 sb = *(const float4*)&state[base + 4];
        float4 aa = *(const float4*)&g_att[base];
        float4 ab = *(const float4*)&g_att[base + 4];
        float z[8] = {sa.x+aa.x, sa.y+aa.y, sa.z+aa.z, sa.w+aa.w,
                      sb.x+ab.x, sb.y+ab.y, sb.z+ab.z, sb.w+ab.w};
        *(float4*)&z1s[tok*64 + c8]     = make_float4(z[0], z[1], z[2], z[3]);
        *(float4*)&z1s[tok*64 + c8 + 4] = make_float4(z[4], z[5], z[6], z[7]);
        float s1 = 0.f, s2 = 0.f;
        #pragma unroll
        for (int i = 0; i < 8; i++) { s1 += z[i]; s2 += z[i]*z[i]; }
        #pragma unroll
        for (int o = 1; o < 8; o <<= 1) {
            s1 += __shfl_xor_sync(0xffffffffu, s1, o);
            s2 += __shfl_xor_sync(0xffffffffu, s2, o);
        }
        float m = s1 * (1.0f/64.0f);
        float var = s2 * (1.0f/64.0f) - m*m;
        float r = rsqrtf(var + 1e-5f);
        float4 ga = *(const float4*)&g1[c8],    gb = *(const float4*)&g1[c8+4];
        float4 ba = *(const float4*)&beta1[c8], bb = *(const float4*)&beta1[c8+4];
        float gv[8] = {ga.x,ga.y,ga.z,ga.w,gb.x,gb.y,gb.z,gb.w};
        float bv[8] = {ba.x,ba.y,ba.z,ba.w,bb.x,bb.y,bb.z,bb.w};
        #pragma unroll
        for (int i = 0; i < 8; i++)
            z2s[tok*Z2S + c8 + i] = (z[i] - m) * r * gv[i] + bv[i];
    }
    __syncthreads();

    const int w = tid >> 5, lane = tid & 31;

    // ---- phase2: hidden = gelu(Z2 @ W1 + b1). warp w: channels [32w,32w+32) ----
    {
        int tg = lane >> 2;             // token quad 0..7
        int cg = lane & 3;              // channel octet within slab
        int jbase = w*32 + cg*8;        // 8 hidden channels
        u64 acc[4][4];
        ulonglong2 bb0 = *(const ulonglong2*)&b1[jbase];
        ulonglong2 bb1 = *(const ulonglong2*)&b1[jbase + 4];
        #pragma unroll
        for (int t = 0; t < 4; t++) {
            acc[t][0] = bb0.x; acc[t][1] = bb0.y;
            acc[t][2] = bb1.x; acc[t][3] = bb1.y;
        }
        #pragma unroll 2
        for (int k = 0; k < 64; k++) {
            float a0 = z2s[(4*tg+0)*Z2S + k];
            float a1 = z2s[(4*tg+1)*Z2S + k];
            float a2 = z2s[(4*tg+2)*Z2S + k];
            float a3 = z2s[(4*tg+3)*Z2S + k];
            u64 ad0 = dup2(a0), ad1 = dup2(a1), ad2 = dup2(a2), ad3 = dup2(a3);
            ulonglong2 w01 = *(const ulonglong2*)&W1[k*256 + jbase];
            ulonglong2 w23 = *(const ulonglong2*)&W1[k*256 + jbase + 4];
            fma2(acc[0][0], ad0, w01.x); fma2(acc[0][1], ad0, w01.y);
            fma2(acc[0][2], ad0, w23.x); fma2(acc[0][3], ad0, w23.y);
            fma2(acc[1][0], ad1, w01.x); fma2(acc[1][1], ad1, w01.y);
            fma2(acc[1][2], ad1, w23.x); fma2(acc[1][3], ad1, w23.y);
            fma2(acc[2][0], ad2, w01.x); fma2(acc[2][1], ad2, w01.y);
            fma2(acc[2][2], ad2, w23.x); fma2(acc[2][3], ad2, w23.y);
            fma2(acc[3][0], ad3, w01.x); fma2(acc[3][1], ad3, w01.y);
            fma2(acc[3][2], ad3, w23.x); fma2(acc[3][3], ad3, w23.y);
        }
        #pragma unroll
        for (int t = 0; t < 4; t++) {
            float2 v0 = unpack2(acc[t][0]);
            float2 v1 = unpack2(acc[t][1]);
            float2 v2 = unpack2(acc[t][2]);
            float2 v3 = unpack2(acc[t][3]);
            int row = (4*tg + t) * HHS + jbase;
            *(float4*)&hhs[row]     = make_float4(gelu_erf(v0.x), gelu_erf(v0.y),
                                                  gelu_erf(v1.x), gelu_erf(v1.y));
            *(float4*)&hhs[row + 4] = make_float4(gelu_erf(v2.x), gelu_erf(v2.y),
                                                  gelu_erf(v3.x), gelu_erf(v3.y));
        }
    }
    __syncthreads();

    // ---- phase3: Z4 = hidden @ W2 + b2; out = Z1 + Z4. thread: 2 tok x 4 ch ----
    {
        int tg3 = lane >> 4;            // 0..1
        int cg3 = lane & 15;            // 0..15
        int tokA = w*4 + tg3*2;         // tokens tokA, tokA+1
        int cc = cg3 * 4;               // channels cc..cc+3
        u64 oa[2][2];
        ulonglong2 b2v = *(const ulonglong2*)&b2[cc];
        oa[0][0] = b2v.x; oa[0][1] = b2v.y;
        oa[1][0] = b2v.x; oa[1][1] = b2v.y;
        #pragma unroll 4
        for (int j = 0; j < 256; j++) {
            float h0 = hhs[tokA*HHS + j];
            float h1 = hhs[(tokA+1)*HHS + j];
            u64 hd0 = dup2(h0), hd1 = dup2(h1);
            ulonglong2 wv = *(const ulonglong2*)&W2[j*64 + cc];
            fma2(oa[0][0], hd0, wv.x); fma2(oa[0][1], hd0, wv.y);
            fma2(oa[1][0], hd1, wv.x); fma2(oa[1][1], hd1, wv.y);
        }
        #pragma unroll
        for (int t = 0; t < 2; t++) {
            float2 p0 = unpack2(oa[t][0]);
            float2 p1 = unpack2(oa[t][1]);
            float4 z1r = *(const float4*)&z1s[(tokA+t)*64 + cc];
            *(float4*)&out[(t0 + tokA + t)*64 + cc] =
                make_float4(z1r.x + p0.x, z1r.y + p0.y, z1r.z + p1.x, z1r.w + p1.y);
        }
    }
}

// ---------------------------------------------------------------------------
extern "C" void kernel_launch(void* const* d_in, const int* in_sizes, int n_in,
                              void* d_out, int out_size)
{
    const float* state = (const float*)d_in[0];
    const float* Hin   = (const float*)d_in[1];
    const float* Wq  = (const float*)d_in[2];  const float* bq  = (const float*)d_in[3];
    const float* Wk  = (const float*)d_in[4];  const float* bk  = (const float*)d_in[5];
    const float* Wv  = (const float*)d_in[6];  const float* bv  = (const float*)d_in[7];
    const float* Wcq = (const float*)d_in[8];  const float* bcq = (const float*)d_in[9];
    const float* Wck = (const float*)d_in[10]; const float* bck = (const float*)d_in[11];
    const float* Wcv = (const float*)d_in[12]; const float* bcv = (const float*)d_in[13];
    const float* gQE = (const float*)d_in[14]; const float* bQE = (const float*)d_in[15];
    const float* gKE = (const float*)d_in[16]; const float* bKE = (const float*)d_in[17];
    const float* gVE = (const float*)d_in[18]; const float* bVE = (const float*)d_in[19];
    const float* gQH = (const float*)d_in[20]; const float* bQH = (const float*)d_in[21];
    const float* gKH = (const float*)d_in[22]; const float* bKH = (const float*)d_in[23];
    const float* gVH = (const float*)d_in[24]; const float* bVH = (const float*)d_in[25];
    const float* W1  = (const float*)d_in[26]; const float* b1  = (const float*)d_in[27];
    const float* W2  = (const float*)d_in[28]; const float* b2  = (const float*)d_in[29];
    const float* g1  = (const float*)d_in[30]; const float* be1 = (const float*)d_in[31];
    float* out = (float*)d_out;

    const int attn_smem = ATTN_SMEM_FLOATS * (int)sizeof(float);   // 82224 B
    cudaFuncSetAttribute(attn_kernel,
                         cudaFuncAttributeMaxDynamicSharedMemorySize, attn_smem);
    const int ffn_smem = FFN_SMEM_FLOATS * (int)sizeof(float);     // 49792 B
    cudaFuncSetAttribute(ffn_kernel,
                         cudaFuncAttributeMaxDynamicSharedMemorySize, ffn_smem);

    qkv_kernel<<<TOKENS/QTOK, 192>>>(state, Hin,
        Wq, bq, Wk, bk, Wv, bv, Wcq, bcq, Wck, bck, Wcv, bcv,
        gQE, bQE, gKE, bKE, gVE, bVE, gQH, bQH, gKH, bKH, gVH, bVH);

    attn_kernel<<<dim3(10, BATCH*2), 256, attn_smem>>>();

    ffn_kernel<<<TOKENS/32, 256, ffn_smem>>>(state, W1, b1, W2, b2, g1, be1, out);
}